// round 11
// baseline (speedup 1.0000x reference)
#include <cuda_runtime.h>
#include <cuda_bf16.h>
#include <cstdint>
#include <math.h>

// ---------------- problem constants ----------------
#define B_     64
#define HID_   2048
#define NH_    32
#define NKV_   8
#define HD_    64
#define G_     4          // NH/NKV
#define BS_    16
#define MAXB_  128
#define MAXKV_ 2048
#define QKVN_  3072       // NH*HD + 2*NKV*HD
#define SCALE_ 0.125f     // 64^-0.5
#define SPLIT_ 8          // KV splits per (b, kv-head)
#define SCP_   264        // scs row stride (floats), 264%32==8 -> conflict-free

// ---------------- scratch: device globals only ----------------
__device__ float g_qkv [B_ * QKVN_];
__device__ float g_q   [B_ * NH_ * HD_];
__device__ float g_k   [B_ * NKV_ * HD_];
__device__ float g_att [B_ * NH_ * HD_];
__device__ float g_part[4718592];               // GEMM split partials (18.9MB)
__device__ float g_pmax[B_ * NKV_ * SPLIT_ * G_];
__device__ float g_psum[B_ * NKV_ * SPLIT_ * G_];
__device__ float g_pout[B_ * NKV_ * SPLIT_ * G_ * HD_];

// ---------------- cp.async helpers (GEMM only) ----------------
__device__ __forceinline__ void cpa16(void* smem, const void* gptr) {
    unsigned a = (unsigned)__cvta_generic_to_shared(smem);
    asm volatile("cp.async.cg.shared.global [%0], [%1], 16;\n" :: "r"(a), "l"(gptr));
}
#define CPA_COMMIT() asm volatile("cp.async.commit_group;\n")
#define CPA_WAIT0()  asm volatile("cp.async.wait_group 0;\n")
#define CPA_WAIT1()  asm volatile("cp.async.wait_group 1;\n")

// ============================================================================
// GEMM: part[split] = A(64xKchunk) * B(KchunkxN); BM64 BN256 BK16, 8x8 micro,
// cp.async double-buffered, STG epilogue.
// ============================================================================
__device__ __forceinline__ void gemm_body(
    const float* __restrict__ A, const float* __restrict__ B,
    int N, int K, int kb0, int nkb, int split)
{
    __shared__ float As[2][64 * 16];
    __shared__ float Bs[2][16][256];

    int n0 = blockIdx.x * 256;
    int t  = threadIdx.x;
    int tx = t & 31, ty = t >> 5;
    int r0 = ty * 8, c0 = tx * 8;
    int a_row = t >> 2, a_c4 = t & 3;

    float acc[8][8];
#pragma unroll
    for (int i = 0; i < 8; i++)
#pragma unroll
        for (int j = 0; j < 8; j++) acc[i][j] = 0.f;

    cpa16(&As[0][a_row * 16 + a_c4 * 4], &A[(size_t)a_row * K + kb0 + a_c4 * 4]);
#pragma unroll
    for (int r = 0; r < 4; r++) {
        int id = t + 256 * r, row = id >> 6, col4 = id & 63;
        cpa16(&Bs[0][row][col4 * 4], &B[(size_t)(kb0 + row) * N + n0 + col4 * 4]);
    }
    CPA_COMMIT();

    for (int kt = 0; kt < nkb; kt++) {
        int buf = kt & 1;
        if (kt + 1 < nkb) {
            int kb = kb0 + (kt + 1) * 16, nb = buf ^ 1;
            cpa16(&As[nb][a_row * 16 + a_c4 * 4], &A[(size_t)a_row * K + kb + a_c4 * 4]);
#pragma unroll
            for (int r = 0; r < 4; r++) {
                int id = t + 256 * r, row = id >> 6, col4 = id & 63;
                cpa16(&Bs[nb][row][col4 * 4], &B[(size_t)(kb + row) * N + n0 + col4 * 4]);
            }
            CPA_COMMIT();
            CPA_WAIT1();
        } else {
            CPA_WAIT0();
        }
        __syncthreads();
#pragma unroll
        for (int kk = 0; kk < 16; kk++) {
            float am[8];
#pragma unroll
            for (int i = 0; i < 8; i++) am[i] = As[buf][(r0 + i) * 16 + kk];
            float4 b0 = *(const float4*)&Bs[buf][kk][c0];
            float4 b1 = *(const float4*)&Bs[buf][kk][c0 + 4];
            float bn[8] = {b0.x, b0.y, b0.z, b0.w, b1.x, b1.y, b1.z, b1.w};
#pragma unroll
            for (int i = 0; i < 8; i++)
#pragma unroll
                for (int j = 0; j < 8; j++) acc[i][j] += am[i] * bn[j];
        }
        __syncthreads();
    }

    float* dst = g_part + (size_t)split * (64 * N);
#pragma unroll
    for (int i = 0; i < 8; i++) {
        float* row = dst + (size_t)(r0 + i) * N + n0 + c0;
        *(float4*)&row[0] = make_float4(acc[i][0], acc[i][1], acc[i][2], acc[i][3]);
        *(float4*)&row[4] = make_float4(acc[i][4], acc[i][5], acc[i][6], acc[i][7]);
    }
}

__global__ __launch_bounds__(256) void gemm_qkv_kernel(
    const float* __restrict__ A, const float* __restrict__ B)
{
    int s = blockIdx.y;
    int kb0 = (s * 5 + min(s, 8)) * 16;
    int nkb = 5 + (s < 8 ? 1 : 0);
    gemm_body(A, B, QKVN_, HID_, kb0, nkb, s);
}
__global__ __launch_bounds__(256) void gemm_out_kernel(const float* __restrict__ B)
{
    int s = blockIdx.y;
    int kb0 = (s * 3 + min(s, 20)) * 16;
    int nkb = 3 + (s < 20 ? 1 : 0);
    gemm_body(g_att, B, HID_, NH_ * HD_, kb0, nkb, s);
}

// ---------------- split reductions (float4) ----------------
__global__ void reduce_qkv_kernel() {
    int i = blockIdx.x * 256 + threadIdx.x;    // n4 = 49152
    const float4* p = (const float4*)g_part;
    float4 s = p[i];
#pragma unroll
    for (int k = 1; k < 24; k++) {
        float4 v = p[(size_t)k * 49152 + i];
        s.x += v.x; s.y += v.y; s.z += v.z; s.w += v.w;
    }
    ((float4*)g_qkv)[i] = s;
}
__global__ void reduce_out_kernel(float* __restrict__ out) {
    int i = blockIdx.x * 256 + threadIdx.x;    // n4 = 32768
    const float4* p = (const float4*)g_part;
    float4 s = p[i];
#pragma unroll
    for (int k = 1; k < 36; k++) {
        float4 v = p[(size_t)k * 32768 + i];
        s.x += v.x; s.y += v.y; s.z += v.z; s.w += v.w;
    }
    ((float4*)out)[i] = s;
}

// ---------------- RMSNorm + RoPE ----------------
__global__ __launch_bounds__(256) void prep_kernel(
    const int* __restrict__ positions,
    const float* __restrict__ qw, const float* __restrict__ kw)
{
    int b = blockIdx.x;
    int t = threadIdx.x, w = t >> 5, lane = t & 31;
    __shared__ float cs[32], sn[32];

    int pos = positions[b];
    if (t < 32) {
        double v = 1.0;
        if (t & 1)  v *= 0.6493816315762113;
        if (t & 2)  v *= 0.4216965034285822;
        if (t & 4)  v *= 0.17782794100389228;
        if (t & 8)  v *= 0.03162277660168379;
        if (t & 16) v *= 0.001;
        double ang = (double)pos * v;
        double k = floor(ang * 0.15915494309189535);
        float r = (float)(ang - k * 6.283185307179586);
        cs[t] = cosf(r);
        sn[t] = sinf(r);
    }
    __syncthreads();

    const float* row = g_qkv + (size_t)b * QKVN_;
    for (int h = w; h < NH_ + NKV_; h += 8) {
        bool isq = (h < NH_);
        const float* src = isq ? row + h * HD_ : row + NH_ * HD_ + (h - NH_) * HD_;
        float x1 = src[lane], x2 = src[lane + 32];
        float ss = x1 * x1 + x2 * x2;
#pragma unroll
        for (int o = 16; o; o >>= 1) ss += __shfl_xor_sync(0xffffffffu, ss, o);
        float inv = rsqrtf(ss * (1.f / 64.f) + 1e-5f);
        const float* lw = isq ? qw : kw;
        x1 *= inv * lw[lane];
        x2 *= inv * lw[lane + 32];
        float c = cs[lane], s = sn[lane];
        float y1 = x1 * c - x2 * s;
        float y2 = x2 * c + x1 * s;
        float* dst = isq ? g_q + ((size_t)b * NH_ + h) * HD_
                         : g_k + ((size_t)b * NKV_ + (h - NH_)) * HD_;
        dst[lane]      = y1;
        dst[lane + 32] = y2;
    }
}

// ============================================================================
// Split-KV attention, barrier-free streaming. One CTA per (kv, b, split).
// Pass1: thread=(pos,oct); K direct LDG.128 x2; q in registers; butterfly.
// Pass3: thread=(dim,sg); V direct LDG.32; probs float4 LDS broadcast.
// smem ~9 KB.
// ============================================================================
__global__ __launch_bounds__(256) void attn_split_kernel(
    const float* __restrict__ kc, const float* __restrict__ vc,
    const int* __restrict__ ctxlens, const int* __restrict__ btab)
{
    __shared__ float scs[G_ * SCP_];       // 4224 B scores/probs
    __shared__ float aux[1024];            // 4096 B epilogue reduce
    __shared__ float redm[8][4];
    __shared__ float gmax[G_], gsum[G_];
    __shared__ int   sbt[MAXB_];

    int kv = blockIdx.x, b = blockIdx.y, sp = blockIdx.z;
    int t = threadIdx.x, w = t >> 5, lane = t & 31;
    int ctx = ctxlens[b];
    ctx = ctx < 1 ? 1 : (ctx > MAXKV_ ? MAXKV_ : ctx);

    int chunk = (ctx + SPLIT_ - 1) / SPLIT_;
    int c0 = sp * chunk;
    int cn = min(chunk, ctx - c0);
    int pbase = ((b * NKV_ + kv) * SPLIT_ + sp) * G_;

    if (cn <= 0) {
        if (t < G_) { g_pmax[pbase + t] = -1e30f; g_psum[pbase + t] = 0.f; }
        g_pout[(size_t)(pbase + (t >> 6)) * HD_ + (t & 63)] = 0.f;
        return;
    }

    if (t < MAXB_) sbt[t] = btab[b * MAXB_ + t];
    if (t < G_)    gsum[t] = 0.f;

    const float* knew_p = g_k + ((size_t)b * NKV_ + kv) * HD_;
    const float* vnew_p = g_qkv + (size_t)b * QKVN_ + NH_ * HD_ + NKV_ * HD_ + kv * HD_;

    // ---- pass 1: scores, barrier-free streaming ----
    int p = t >> 3, oct = t & 7;
    int g = (oct & 1) * 2 + ((oct >> 1) & 1);   // butterfly ownership
    // q fragments in registers (loaded once from global)
    float4 qA[4], qB[4];
#pragma unroll
    for (int gg = 0; gg < 4; gg++) {
        const float* qrow = g_q + ((size_t)b * NH_ + kv * G_ + gg) * HD_;
        qA[gg] = *(const float4*)(qrow + oct * 4);
        qB[gg] = *(const float4*)(qrow + (oct + 8) * 4);
    }
    __syncthreads();   // sbt visible

    int niter = (cn + 31) >> 5;
    int cnp = niter << 5;                 // padded length, <= 256
    float m_loc = -1e30f;

    for (int i = 0; i < niter; i++) {
        int sl = p + (i << 5);
        int s = c0 + sl;
        bool valid = (sl < cn);
        const float* kp = knew_p;         // safe dummy
        if (valid && s != ctx - 1)
            kp = kc + (((size_t)sbt[s >> 4] * BS_ + (s & 15)) * NKV_ + kv) * HD_;
        float4 kA = *(const float4*)(kp + oct * 4);
        float4 kB = *(const float4*)(kp + (oct + 8) * 4);
        float dots[4];
#pragma unroll
        for (int gg = 0; gg < 4; gg++) {
            dots[gg] = qA[gg].x * kA.x + qA[gg].y * kA.y + qA[gg].z * kA.z + qA[gg].w * kA.w
                     + qB[gg].x * kB.x + qB[gg].y * kB.y + qB[gg].z * kB.z + qB[gg].w * kB.w;
        }
        bool b0 = oct & 1, b1 = oct & 2;
        float s1 = b0 ? dots[0] : dots[2];
        float r1 = __shfl_xor_sync(0xffffffffu, s1, 1);
        if (!b0) dots[0] += r1; else dots[2] += r1;
        float s2 = b0 ? dots[1] : dots[3];
        float r2 = __shfl_xor_sync(0xffffffffu, s2, 1);
        if (!b0) dots[1] += r2; else dots[3] += r2;
        float v0 = b0 ? dots[2] : dots[0];
        float v1 = b0 ? dots[3] : dots[1];
        float s3 = b1 ? v0 : v1;
        float r3 = __shfl_xor_sync(0xffffffffu, s3, 2);
        float v = (b1 ? v1 : v0) + r3;
        v += __shfl_xor_sync(0xffffffffu, v, 4);
        float fin = valid ? v * SCALE_ : -1e30f;
        if (oct < 4) scs[g * SCP_ + sl] = fin;
        m_loc = fmaxf(m_loc, fin);
    }
    // per-g max reduce
    m_loc = fmaxf(m_loc, __shfl_xor_sync(0xffffffffu, m_loc, 8));
    m_loc = fmaxf(m_loc, __shfl_xor_sync(0xffffffffu, m_loc, 16));
    if (lane < 4) redm[w][g] = m_loc;
    __syncthreads();
    if (t < G_) {
        float mm = redm[0][t];
#pragma unroll
        for (int ww = 1; ww < 8; ww++) mm = fmaxf(mm, redm[ww][t]);
        gmax[t] = mm;
    }
    __syncthreads();

    // ---- pass 2: exp + sum over padded range (pad scores -1e30 -> 0) ----
#pragma unroll
    for (int gg = 0; gg < G_; gg++) {
        float mg = gmax[gg];
        float acc = 0.f;
        for (int s = t; s < cnp; s += 256) {
            float pe = __expf(scs[gg * SCP_ + s] - mg);
            scs[gg * SCP_ + s] = pe;
            acc += pe;
        }
#pragma unroll
        for (int o = 16; o; o >>= 1) acc += __shfl_xor_sync(0xffffffffu, acc, o);
        if (lane == 0) atomicAdd(&gsum[gg], acc);
    }
    __syncthreads();

    // ---- pass 3: streaming V, thread=(d, sg); probs broadcast; unguarded ----
    int d = t & 63, sg = t >> 6;
    float oa0 = 0.f, oa1 = 0.f, oa2 = 0.f, oa3 = 0.f;
    int nsup = cnp >> 4;                  // 16-position superblocks
    const float4* s4 = (const float4*)scs;   // row stride SCP_/4 = 66 per g
    for (int i = 0; i < nsup; i++) {
        int sb = (i << 4) + (sg << 2);    // 4 positions
        int f = sb >> 2;
        float4 pa = s4[0 * 66 + f];
        float4 pb = s4[1 * 66 + f];
        float4 pc = s4[2 * 66 + f];
        float4 pd = s4[3 * 66 + f];
        float vv[4];
#pragma unroll
        for (int j = 0; j < 4; j++) {
            int s = c0 + sb + j;
            const float* vp = (s == ctx - 1) ? vnew_p
                : vc + (((size_t)sbt[s >> 4] * BS_ + (s & 15)) * NKV_ + kv) * HD_;
            vv[j] = vp[d];
        }
        oa0 += pa.x * vv[0] + pa.y * vv[1] + pa.z * vv[2] + pa.w * vv[3];
        oa1 += pb.x * vv[0] + pb.y * vv[1] + pb.z * vv[2] + pb.w * vv[3];
        oa2 += pc.x * vv[0] + pc.y * vv[1] + pc.z * vv[2] + pc.w * vv[3];
        oa3 += pd.x * vv[0] + pd.y * vv[1] + pd.z * vv[2] + pd.w * vv[3];
    }
    // reduce partial outputs over 4 s-groups via aux
    __syncthreads();
    aux[sg * 256 + 0 * 64 + d] = oa0;
    aux[sg * 256 + 1 * 64 + d] = oa1;
    aux[sg * 256 + 2 * 64 + d] = oa2;
    aux[sg * 256 + 3 * 64 + d] = oa3;
    __syncthreads();
    {
        int g2 = t >> 6, d2 = t & 63;
        float oo = aux[0 * 256 + g2 * 64 + d2] + aux[1 * 256 + g2 * 64 + d2]
                 + aux[2 * 256 + g2 * 64 + d2] + aux[3 * 256 + g2 * 64 + d2];
        g_pout[(size_t)(pbase + g2) * HD_ + d2] = oo;
    }
    if (t < G_) { g_pmax[pbase + t] = gmax[t]; g_psum[pbase + t] = gsum[t]; }
}

// ---------------- combine splits: one CTA per (kv, b) ----------------
__global__ __launch_bounds__(256) void attn_combine_kernel()
{
    int kv = blockIdx.x, b = blockIdx.y;
    int t = threadIdx.x, g = t >> 6, d = t & 63;
    int base = (b * NKV_ + kv) * SPLIT_ * G_;

    float mi[SPLIT_];
    float M = -1e30f;
#pragma unroll
    for (int i = 0; i < SPLIT_; i++) {
        mi[i] = g_pmax[base + i * G_ + g];
        M = fmaxf(M, mi[i]);
    }
    float denom = 0.f, numer = 0.f;
#pragma unroll
    for (int i = 0; i < SPLIT_; i++) {
        float wgt = __expf(mi[i] - M);
        denom += wgt * g_psum[base + i * G_ + g];
        numer += wgt * g_pout[(size_t)(base + i * G_ + g) * HD_ + d];
    }
    g_att[(size_t)b * (NH_ * HD_) + (kv * G_ + g) * HD_ + d] = numer / denom;
}

// ---------------- launch: kernel launches ONLY ----------------
extern "C" void kernel_launch(void* const* d_in, const int* in_sizes, int n_in,
                              void* d_out, int out_size)
{
    const float* hidden    = (const float*)d_in[0];
    const int*   positions = (const int*)  d_in[1];
    const int*   ctxlens   = (const int*)  d_in[2];
    // d_in[3] slot_mapping unused: phys(ctx-1) == slot, new k/v read directly
    const int*   btab      = (const int*)  d_in[4];
    const float* kc        = (const float*)d_in[5];
    const float* vc        = (const float*)d_in[6];
    const float* wqkv      = (const float*)d_in[7];
    const float* wout      = (const float*)d_in[8];
    const float* qlw       = (const float*)d_in[9];
    const float* klw       = (const float*)d_in[10];
    float* out = (float*)d_out;

    gemm_qkv_kernel<<<dim3(12, 24), 256>>>(hidden, wqkv);
    reduce_qkv_kernel<<<192, 256>>>();
    prep_kernel<<<B_, 256>>>(positions, qlw, klw);
    attn_split_kernel<<<dim3(NKV_, B_, SPLIT_), 256>>>(kc, vc, ctxlens, btab);
    attn_combine_kernel<<<dim3(NKV_, B_), 256>>>();
    gemm_out_kernel<<<dim3(8, 36), 256>>>(wout);
    reduce_out_kernel<<<128, 256>>>(out);
}

// round 12
// speedup vs baseline: 1.3508x; 1.3508x over previous
#include <cuda_runtime.h>
#include <cuda_bf16.h>
#include <cstdint>
#include <math.h>

// ---------------- problem constants ----------------
#define B_     64
#define HID_   2048
#define NH_    32
#define NKV_   8
#define HD_    64
#define G_     4          // NH/NKV
#define BS_    16
#define MAXB_  128
#define MAXKV_ 2048
#define QKVN_  3072       // NH*HD + 2*NKV*HD
#define SCALE_ 0.125f     // 64^-0.5
#define T_     32         // attention KV tile (positions)
#define NBUF_  3          // cp.async pipeline depth
#define SPLIT_ 8          // KV splits per (b, kv-head)
#define SCP_   264        // scs row stride (floats), 264%32==8 -> conflict-free

// ---------------- scratch: device globals only ----------------
__device__ float g_qkv [B_ * QKVN_];
__device__ float g_q   [B_ * NH_ * HD_];
__device__ float g_k   [B_ * NKV_ * HD_];
__device__ float g_att [B_ * NH_ * HD_];
__device__ float g_part[4718592];               // GEMM split partials (18.9MB)
__device__ float g_psum[B_ * NKV_ * SPLIT_ * G_];
__device__ float g_pout[B_ * NKV_ * SPLIT_ * G_ * HD_];

// ---------------- cp.async helpers ----------------
__device__ __forceinline__ void cpa16(void* smem, const void* gptr) {
    unsigned a = (unsigned)__cvta_generic_to_shared(smem);
    asm volatile("cp.async.cg.shared.global [%0], [%1], 16;\n" :: "r"(a), "l"(gptr));
}
__device__ __forceinline__ void cpa16z(void* smem, const void* gptr, bool v) {
    unsigned a = (unsigned)__cvta_generic_to_shared(smem);
    int sz = v ? 16 : 0;
    asm volatile("cp.async.cg.shared.global [%0], [%1], 16, %2;\n"
                 :: "r"(a), "l"(gptr), "r"(sz));
}
#define CPA_COMMIT() asm volatile("cp.async.commit_group;\n")
#define CPA_WAIT0()  asm volatile("cp.async.wait_group 0;\n")
#define CPA_WAIT1()  asm volatile("cp.async.wait_group 1;\n")
#define CPA_WAIT2()  asm volatile("cp.async.wait_group 2;\n")

// ============================================================================
// GEMM: part[split] = A(64xKchunk) * B(KchunkxN); BM64 BN256 BK16, 8x8 micro,
// cp.async double-buffered, STG epilogue.
// ============================================================================
__device__ __forceinline__ void gemm_body(
    const float* __restrict__ A, const float* __restrict__ B,
    int N, int K, int kb0, int nkb, int split)
{
    __shared__ float As[2][64 * 16];
    __shared__ float Bs[2][16][256];

    int n0 = blockIdx.x * 256;
    int t  = threadIdx.x;
    int tx = t & 31, ty = t >> 5;
    int r0 = ty * 8, c0 = tx * 8;
    int a_row = t >> 2, a_c4 = t & 3;

    float acc[8][8];
#pragma unroll
    for (int i = 0; i < 8; i++)
#pragma unroll
        for (int j = 0; j < 8; j++) acc[i][j] = 0.f;

    cpa16(&As[0][a_row * 16 + a_c4 * 4], &A[(size_t)a_row * K + kb0 + a_c4 * 4]);
#pragma unroll
    for (int r = 0; r < 4; r++) {
        int id = t + 256 * r, row = id >> 6, col4 = id & 63;
        cpa16(&Bs[0][row][col4 * 4], &B[(size_t)(kb0 + row) * N + n0 + col4 * 4]);
    }
    CPA_COMMIT();

    for (int kt = 0; kt < nkb; kt++) {
        int buf = kt & 1;
        if (kt + 1 < nkb) {
            int kb = kb0 + (kt + 1) * 16, nb = buf ^ 1;
            cpa16(&As[nb][a_row * 16 + a_c4 * 4], &A[(size_t)a_row * K + kb + a_c4 * 4]);
#pragma unroll
            for (int r = 0; r < 4; r++) {
                int id = t + 256 * r, row = id >> 6, col4 = id & 63;
                cpa16(&Bs[nb][row][col4 * 4], &B[(size_t)(kb + row) * N + n0 + col4 * 4]);
            }
            CPA_COMMIT();
            CPA_WAIT1();
        } else {
            CPA_WAIT0();
        }
        __syncthreads();
#pragma unroll
        for (int kk = 0; kk < 16; kk++) {
            float am[8];
#pragma unroll
            for (int i = 0; i < 8; i++) am[i] = As[buf][(r0 + i) * 16 + kk];
            float4 b0 = *(const float4*)&Bs[buf][kk][c0];
            float4 b1 = *(const float4*)&Bs[buf][kk][c0 + 4];
            float bn[8] = {b0.x, b0.y, b0.z, b0.w, b1.x, b1.y, b1.z, b1.w};
#pragma unroll
            for (int i = 0; i < 8; i++)
#pragma unroll
                for (int j = 0; j < 8; j++) acc[i][j] += am[i] * bn[j];
        }
        __syncthreads();
    }

    float* dst = g_part + (size_t)split * (64 * N);
#pragma unroll
    for (int i = 0; i < 8; i++) {
        float* row = dst + (size_t)(r0 + i) * N + n0 + c0;
        *(float4*)&row[0] = make_float4(acc[i][0], acc[i][1], acc[i][2], acc[i][3]);
        *(float4*)&row[4] = make_float4(acc[i][4], acc[i][5], acc[i][6], acc[i][7]);
    }
}

__global__ __launch_bounds__(256) void gemm_qkv_kernel(
    const float* __restrict__ A, const float* __restrict__ B)
{
    int s = blockIdx.y;
    int kb0 = (s * 5 + min(s, 8)) * 16;
    int nkb = 5 + (s < 8 ? 1 : 0);
    gemm_body(A, B, QKVN_, HID_, kb0, nkb, s);
}
__global__ __launch_bounds__(256) void gemm_out_kernel(const float* __restrict__ B)
{
    int s = blockIdx.y;
    int kb0 = (s * 3 + min(s, 20)) * 16;
    int nkb = 3 + (s < 20 ? 1 : 0);
    gemm_body(g_att, B, HID_, NH_ * HD_, kb0, nkb, s);
}

// ---------------- split reductions (float4) ----------------
__global__ void reduce_qkv_kernel() {
    int i = blockIdx.x * 256 + threadIdx.x;    // n4 = 49152
    const float4* p = (const float4*)g_part;
    float4 s = p[i];
#pragma unroll
    for (int k = 1; k < 24; k++) {
        float4 v = p[(size_t)k * 49152 + i];
        s.x += v.x; s.y += v.y; s.z += v.z; s.w += v.w;
    }
    ((float4*)g_qkv)[i] = s;
}
__global__ void reduce_out_kernel(float* __restrict__ out) {
    int i = blockIdx.x * 256 + threadIdx.x;    // n4 = 32768
    const float4* p = (const float4*)g_part;
    float4 s = p[i];
#pragma unroll
    for (int k = 1; k < 36; k++) {
        float4 v = p[(size_t)k * 32768 + i];
        s.x += v.x; s.y += v.y; s.z += v.z; s.w += v.w;
    }
    ((float4*)out)[i] = s;
}

// ---------------- RMSNorm + RoPE ----------------
__global__ __launch_bounds__(256) void prep_kernel(
    const int* __restrict__ positions,
    const float* __restrict__ qw, const float* __restrict__ kw)
{
    int b = blockIdx.x;
    int t = threadIdx.x, w = t >> 5, lane = t & 31;
    __shared__ float cs[32], sn[32];

    int pos = positions[b];
    if (t < 32) {
        double v = 1.0;
        if (t & 1)  v *= 0.6493816315762113;
        if (t & 2)  v *= 0.4216965034285822;
        if (t & 4)  v *= 0.17782794100389228;
        if (t & 8)  v *= 0.03162277660168379;
        if (t & 16) v *= 0.001;
        double ang = (double)pos * v;
        double k = floor(ang * 0.15915494309189535);
        float r = (float)(ang - k * 6.283185307179586);
        cs[t] = cosf(r);
        sn[t] = sinf(r);
    }
    __syncthreads();

    const float* row = g_qkv + (size_t)b * QKVN_;
    for (int h = w; h < NH_ + NKV_; h += 8) {
        bool isq = (h < NH_);
        const float* src = isq ? row + h * HD_ : row + NH_ * HD_ + (h - NH_) * HD_;
        float x1 = src[lane], x2 = src[lane + 32];
        float ss = x1 * x1 + x2 * x2;
#pragma unroll
        for (int o = 16; o; o >>= 1) ss += __shfl_xor_sync(0xffffffffu, ss, o);
        float inv = rsqrtf(ss * (1.f / 64.f) + 1e-5f);
        const float* lw = isq ? qw : kw;
        x1 *= inv * lw[lane];
        x2 *= inv * lw[lane + 32];
        float c = cs[lane], s = sn[lane];
        float y1 = x1 * c - x2 * s;
        float y2 = x2 * c + x1 * s;
        float* dst = isq ? g_q + ((size_t)b * NH_ + h) * HD_
                         : g_k + ((size_t)b * NKV_ + (h - NH_)) * HD_;
        dst[lane]      = y1;
        dst[lane + 32] = y2;
    }
}

// ============================================================================
// Split-KV attention, shift-free softmax (|score| <= 8 by rmsnorm bound).
// T=32 tiles, 3-deep cp.async pipeline. Pass1 fuses exp; no max pass.
// smem ~34 KB -> 6 CTAs/SM.
// ============================================================================
__device__ __forceinline__ void tile_load(
    float* dst, const float* __restrict__ cache, const float* __restrict__ newrow,
    const int* sbt, int kv, int s0, int send, int ctx, int t)
{
    int c = t & 15;
#pragma unroll
    for (int r = 0; r < 2; r++) {
        int p = (t >> 4) + 16 * r;
        int s = s0 + p;
        bool v = (s < send);
        const float* src = cache;
        if (v) {
            if (s == ctx - 1) src = newrow + c * 4;
            else {
                int blk = sbt[s >> 4];
                src = cache + (((size_t)blk * BS_ + (s & 15)) * NKV_ + kv) * HD_ + c * 4;
            }
        }
        cpa16z(dst + p * 64 + c * 4, src, v);
    }
}

__global__ __launch_bounds__(256) void attn_split_kernel(
    const float* __restrict__ kc, const float* __restrict__ vc,
    const int* __restrict__ ctxlens, const int* __restrict__ btab)
{
    __shared__ float kt[NBUF_][T_ * 64];   // 24576 B
    __shared__ float scs[G_ * SCP_];       // 4224 B probs
    __shared__ float aux[1024];            // 4096 B epilogue reduce
    __shared__ float redm[8][4];
    __shared__ int   sbt[MAXB_];

    int kv = blockIdx.x, b = blockIdx.y, sp = blockIdx.z;
    int t = threadIdx.x, w = t >> 5, lane = t & 31;
    int ctx = ctxlens[b];
    ctx = ctx < 1 ? 1 : (ctx > MAXKV_ ? MAXKV_ : ctx);

    int chunk = (ctx + SPLIT_ - 1) / SPLIT_;
    int c0 = sp * chunk;
    int cn = min(chunk, ctx - c0);
    int pbase = ((b * NKV_ + kv) * SPLIT_ + sp) * G_;

    if (cn <= 0) {       // empty split: zero partials (neutral under plain sum)
        if (t < G_) g_psum[pbase + t] = 0.f;
        g_pout[(size_t)(pbase + (t >> 6)) * HD_ + (t & 63)] = 0.f;
        return;
    }

    if (t < MAXB_) sbt[t] = btab[b * MAXB_ + t];

    const float* knew_p = g_k + ((size_t)b * NKV_ + kv) * HD_;
    const float* vnew_p = g_qkv + (size_t)b * QKVN_ + NH_ * HD_ + NKV_ * HD_ + kv * HD_;

    // q fragments in registers (broadcast loads, L1-hit)
    int p = t >> 3, oct = t & 7;
    int g = (oct & 1) * 2 + ((oct >> 1) & 1);   // butterfly ownership
    float4 qA[4], qB[4];
#pragma unroll
    for (int gg = 0; gg < 4; gg++) {
        const float* qrow = g_q + ((size_t)b * NH_ + kv * G_ + gg) * HD_;
        qA[gg] = *(const float4*)(qrow + oct * 4);
        qB[gg] = *(const float4*)(qrow + (oct + 8) * 4);
    }
    __syncthreads();   // sbt visible

    int send = c0 + cn;
    int ntiles = (cn + T_ - 1) / T_;
    float sum_loc = 0.f;

    // ---- pass 1: probs = exp(q.K * scale) -> smem, 3-deep pipeline ----
#pragma unroll
    for (int i = 0; i < 2; i++) {
        if (i < ntiles) tile_load(kt[i], kc, knew_p, sbt, kv, c0 + i * T_, send, ctx, t);
        CPA_COMMIT();
    }
    for (int j = 0; j < ntiles; j++) {
        if (j + 2 < ntiles)
            tile_load(kt[(j + 2) % 3], kc, knew_p, sbt, kv, c0 + (j + 2) * T_, send, ctx, t);
        CPA_COMMIT();
        CPA_WAIT2();
        __syncthreads();
        const float* kb = kt[j % 3] + p * 64;
        float4 kA = *(const float4*)(kb + oct * 4);
        float4 kB = *(const float4*)(kb + (oct + 8) * 4);
        float dots[4];
#pragma unroll
        for (int gg = 0; gg < 4; gg++) {
            dots[gg] = qA[gg].x * kA.x + qA[gg].y * kA.y + qA[gg].z * kA.z + qA[gg].w * kA.w
                     + qB[gg].x * kB.x + qB[gg].y * kB.y + qB[gg].z * kB.z + qB[gg].w * kB.w;
        }
        bool b0 = oct & 1, b1 = oct & 2;
        float s1 = b0 ? dots[0] : dots[2];
        float r1 = __shfl_xor_sync(0xffffffffu, s1, 1);
        if (!b0) dots[0] += r1; else dots[2] += r1;
        float s2 = b0 ? dots[1] : dots[3];
        float r2 = __shfl_xor_sync(0xffffffffu, s2, 1);
        if (!b0) dots[1] += r2; else dots[3] += r2;
        float v0 = b0 ? dots[2] : dots[0];
        float v1 = b0 ? dots[3] : dots[1];
        float s3 = b1 ? v0 : v1;
        float r3 = __shfl_xor_sync(0xffffffffu, s3, 2);
        float v = (b1 ? v1 : v0) + r3;
        v += __shfl_xor_sync(0xffffffffu, v, 4);
        int sl = j * T_ + p;
        float pe = (sl < cn) ? __expf(v * SCALE_) : 0.f;   // shift-free: |v*s|<=8
        if (oct < 4) scs[g * SCP_ + sl] = pe;
        sum_loc += pe;
        __syncthreads();
    }
    // per-g sum: lanes with same oct (xor 8,16); octs 4-7 are duplicates
    sum_loc += __shfl_xor_sync(0xffffffffu, sum_loc, 8);
    sum_loc += __shfl_xor_sync(0xffffffffu, sum_loc, 16);
    if (lane < 4) redm[w][g] = sum_loc;
    __syncthreads();
    if (t < G_) {
        float ss = 0.f;
#pragma unroll
        for (int ww = 0; ww < 8; ww++) ss += redm[ww][t];
        g_psum[pbase + t] = ss;
    }

    // ---- pass 3: out[g][d] = sum_s p[g][s] * V[s][d], 3-deep pipeline ----
    int d = t & 63, sg = t >> 6;
    float oa0 = 0.f, oa1 = 0.f, oa2 = 0.f, oa3 = 0.f;
#pragma unroll
    for (int i = 0; i < 2; i++) {
        if (i < ntiles) tile_load(kt[i], vc, vnew_p, sbt, kv, c0 + i * T_, send, ctx, t);
        CPA_COMMIT();
    }
    for (int j = 0; j < ntiles; j++) {
        if (j + 2 < ntiles)
            tile_load(kt[(j + 2) % 3], vc, vnew_p, sbt, kv, c0 + (j + 2) * T_, send, ctx, t);
        CPA_COMMIT();
        CPA_WAIT2();
        __syncthreads();
        const float* vb = kt[j % 3];
        const float4* s4 = (const float4*)scs;   // row stride SCP_/4 = 66 per g
        int f0 = j * 8 + sg * 2;
#pragma unroll
        for (int i = 0; i < 2; i++) {
            float4 pa = s4[0 * 66 + f0 + i];
            float4 pb = s4[1 * 66 + f0 + i];
            float4 pc = s4[2 * 66 + f0 + i];
            float4 pd = s4[3 * 66 + f0 + i];
            int sb = (sg * 8 + i * 4) * 64 + d;
            float w0 = vb[sb], w1 = vb[sb + 64], w2 = vb[sb + 128], w3 = vb[sb + 192];
            oa0 += pa.x * w0 + pa.y * w1 + pa.z * w2 + pa.w * w3;
            oa1 += pb.x * w0 + pb.y * w1 + pb.z * w2 + pb.w * w3;
            oa2 += pc.x * w0 + pc.y * w1 + pc.z * w2 + pc.w * w3;
            oa3 += pd.x * w0 + pd.y * w1 + pd.z * w2 + pd.w * w3;
        }
        __syncthreads();
    }
    // reduce partial outputs over 4 s-groups via aux
    aux[sg * 256 + 0 * 64 + d] = oa0;
    aux[sg * 256 + 1 * 64 + d] = oa1;
    aux[sg * 256 + 2 * 64 + d] = oa2;
    aux[sg * 256 + 3 * 64 + d] = oa3;
    __syncthreads();
    {
        int g2 = t >> 6, d2 = t & 63;
        float oo = aux[0 * 256 + g2 * 64 + d2] + aux[1 * 256 + g2 * 64 + d2]
                 + aux[2 * 256 + g2 * 64 + d2] + aux[3 * 256 + g2 * 64 + d2];
        g_pout[(size_t)(pbase + g2) * HD_ + d2] = oo;
    }
}

// ---------------- combine splits: plain sums (shift-free softmax) ----------
__global__ __launch_bounds__(256) void attn_combine_kernel()
{
    int kv = blockIdx.x, b = blockIdx.y;
    int t = threadIdx.x, g = t >> 6, d = t & 63;
    int base = (b * NKV_ + kv) * SPLIT_ * G_;

    float denom = 0.f, numer = 0.f;
#pragma unroll
    for (int i = 0; i < SPLIT_; i++) {
        denom += g_psum[base + i * G_ + g];
        numer += g_pout[(size_t)(base + i * G_ + g) * HD_ + d];
    }
    g_att[(size_t)b * (NH_ * HD_) + (kv * G_ + g) * HD_ + d] = numer / denom;
}

// ---------------- launch: kernel launches ONLY ----------------
extern "C" void kernel_launch(void* const* d_in, const int* in_sizes, int n_in,
                              void* d_out, int out_size)
{
    const float* hidden    = (const float*)d_in[0];
    const int*   positions = (const int*)  d_in[1];
    const int*   ctxlens   = (const int*)  d_in[2];
    // d_in[3] slot_mapping unused: phys(ctx-1) == slot, new k/v read directly
    const int*   btab      = (const int*)  d_in[4];
    const float* kc        = (const float*)d_in[5];
    const float* vc        = (const float*)d_in[6];
    const float* wqkv      = (const float*)d_in[7];
    const float* wout      = (const float*)d_in[8];
    const float* qlw       = (const float*)d_in[9];
    const float* klw       = (const float*)d_in[10];
    float* out = (float*)d_out;

    gemm_qkv_kernel<<<dim3(12, 24), 256>>>(hidden, wqkv);
    reduce_qkv_kernel<<<192, 256>>>();
    prep_kernel<<<B_, 256>>>(positions, qlw, klw);
    attn_split_kernel<<<dim3(NKV_, B_, SPLIT_), 256>>>(kc, vc, ctxlens, btab);
    attn_combine_kernel<<<dim3(NKV_, B_), 256>>>();
    gemm_out_kernel<<<dim3(8, 36), 256>>>(wout);
    reduce_out_kernel<<<128, 256>>>(out);
}